// round 15
// baseline (speedup 1.0000x reference)
#include <cuda_runtime.h>
#include <cuda_fp16.h>
#include <math.h>

#define S_LEN  2048
#define E_DIM  1024
#define H_NUM  16
#define D_HEAD 64
#define B_NUM  2
#define M_TOT  (B_NUM * S_LEN)   // 4096

// ---------------- device scratch (all fp16 intermediates) ----------------
__device__ __half g_Xh[(size_t)M_TOT * E_DIM];    // fp16 x
__device__ __half g_Wqh[(size_t)E_DIM * E_DIM];
__device__ __half g_Wkh[(size_t)E_DIM * E_DIM];
__device__ __half g_Wvh[(size_t)E_DIM * E_DIM];
__device__ __half g_Qr[(size_t)M_TOT * E_DIM];    // raw fp16 projections
__device__ __half g_Kr[(size_t)M_TOT * E_DIM];
__device__ __half g_Vh[(size_t)M_TOT * E_DIM];
__device__ __half g_Qh[(size_t)M_TOT * E_DIM];    // normalized fp16 Q (g folded)
__device__ __half g_Kh[(size_t)M_TOT * E_DIM];    // normalized fp16 K
__device__ __half g_Vt[(size_t)B_NUM * E_DIM * S_LEN]; // V^T: [(b*16+h)*64+d][s]

// ---------------- helpers ----------------
__device__ __forceinline__ void mma_f16(float c[4],
                                        unsigned a0, unsigned a1, unsigned a2, unsigned a3,
                                        unsigned b0, unsigned b1) {
    asm volatile(
        "mma.sync.aligned.m16n8k16.row.col.f32.f16.f16.f32 "
        "{%0,%1,%2,%3}, {%4,%5,%6,%7}, {%8,%9}, {%0,%1,%2,%3};"
        : "+f"(c[0]), "+f"(c[1]), "+f"(c[2]), "+f"(c[3])
        : "r"(a0), "r"(a1), "r"(a2), "r"(a3), "r"(b0), "r"(b1));
}

__device__ __forceinline__ void ldsm4(unsigned r[4], unsigned addr) {
    asm volatile("ldmatrix.sync.aligned.m8n8.x4.shared.b16 {%0,%1,%2,%3}, [%4];"
                 : "=r"(r[0]), "=r"(r[1]), "=r"(r[2]), "=r"(r[3]) : "r"(addr));
}

__device__ __forceinline__ unsigned pack_h2(float a, float b) {
    __half2 h = __floats2half2_rn(a, b);
    return *(unsigned*)&h;
}

// 1D bulk async copy gmem->smem, completion via mbarrier complete_tx.
__device__ __forceinline__ void bulk_cp(unsigned smem_dst, const void* gmem_src,
                                        unsigned bytes, unsigned mbar) {
    asm volatile(
        "cp.async.bulk.shared::cta.global.mbarrier::complete_tx::bytes "
        "[%0], [%1], %2, [%3];"
        :: "r"(smem_dst), "l"(gmem_src), "r"(bytes), "r"(mbar) : "memory");
}

#define MBAR_INIT(addr, cnt) \
    asm volatile("mbarrier.init.shared.b64 [%0], %1;" :: "r"(addr), "r"(cnt) : "memory")
#define MBAR_EXPECT(addr, bytes) \
    asm volatile("mbarrier.arrive.expect_tx.shared.b64 _, [%0], %1;" \
                 :: "r"(addr), "r"(bytes) : "memory")

__device__ __forceinline__ void mbar_wait(unsigned addr, unsigned parity) {
    asm volatile(
        "{\n\t"
        ".reg .pred P1;\n\t"
        "WAIT_LOOP_%=:\n\t"
        "mbarrier.try_wait.parity.acquire.cta.shared::cta.b64 P1, [%0], %1, 0x989680;\n\t"
        "@P1 bra.uni WAIT_DONE_%=;\n\t"
        "bra.uni WAIT_LOOP_%=;\n\t"
        "WAIT_DONE_%=:\n\t"
        "}"
        :: "r"(addr), "r"(parity) : "memory");
}

// ---------------------------------------------------------------------------
// Kernel 0: one-shot fp32 -> fp16 conversion for x, Wq, Wk, Wv.
// ---------------------------------------------------------------------------
#define NX4 (M_TOT * E_DIM / 4)     // 1048576
#define NW4 (E_DIM * E_DIM / 4)     // 262144
#define NCVT (NX4 + 3 * NW4)        // 1835008

__global__ void cvt_all(const float* __restrict__ x,  const float* __restrict__ wq,
                        const float* __restrict__ wk, const float* __restrict__ wv)
{
    int i = blockIdx.x * blockDim.x + threadIdx.x;
    if (i >= NCVT) return;
    const float* src;
    __half* dst;
    int j;
    if (i < NX4)                  { src = x;  dst = g_Xh;  j = i; }
    else if (i < NX4 + NW4)       { src = wq; dst = g_Wqh; j = i - NX4; }
    else if (i < NX4 + 2 * NW4)   { src = wk; dst = g_Wkh; j = i - NX4 - NW4; }
    else                          { src = wv; dst = g_Wvh; j = i - NX4 - 2 * NW4; }
    float4 v = ((const float4*)src)[j];
    __half2* d = (__half2*)dst;
    d[2 * j]     = __floats2half2_rn(v.x, v.y);
    d[2 * j + 1] = __floats2half2_rn(v.z, v.w);
}

// ---------------------------------------------------------------------------
// Kernel 1: C = x @ W^T, m16n8k16 fp16 MMA + ldmatrix, BK=64. Staging via
// per-row cp.async.bulk (128B rows -> stride-144B smem) + mbarrier, killing
// the LDGSTS issue bottleneck. 2 stages, 2 mbarriers.
// ---------------------------------------------------------------------------
#define ROWB   144                      // smem row stride bytes (72 halfs)
#define QA_TILE (128 * ROWB)            // 18432 bytes per matrix tile
#define QKV_STAGE_BYTES 32768u          // A (16KB) + B (16KB) payload per stage
#define QKV_A(buf) (64 + (buf) * 2 * QA_TILE)
#define QKV_B(buf) (64 + (buf) * 2 * QA_TILE + QA_TILE)
#define QKV_SMEM (64 + 4 * QA_TILE)     // 73792 B

__global__ __launch_bounds__(256, 2) void qkv_gemm()
{
    extern __shared__ __align__(16) char smc[];
    const unsigned smb = (unsigned)__cvta_generic_to_shared(smc);
    const unsigned mbA[2] = { smb, smb + 8 };

    const int z  = blockIdx.z;
    const __half* W = (z == 0) ? g_Wqh : (z == 1) ? g_Wkh : g_Wvh;
    __half*       C = (z == 0) ? g_Qr  : (z == 1) ? g_Kr  : g_Vh;

    const int m0   = blockIdx.y * 128;
    const int n0   = blockIdx.x * 128;
    const int t    = threadIdx.x;
    const int warp = t >> 5;
    const int lane = t & 31;
    const int wm   = warp >> 2;
    const int wn   = warp & 3;
    const int lr   = lane >> 2;
    const int lc   = lane & 3;

    const int l7 = lane & 7;
    const int jA_row = (lane >> 3) & 1;
    const int jA_col = (lane >> 4) & 1;
    const int jB_row = (lane >> 4) & 1;
    const int jB_col = (lane >> 3) & 1;

    unsigned aoff[4], boff[2];
#pragma unroll
    for (int mi = 0; mi < 4; mi++)
        aoff[mi] = (wm * 64 + mi * 16 + jA_row * 8 + l7) * ROWB + jA_col * 16;
#pragma unroll
    for (int nip = 0; nip < 2; nip++)
        boff[nip] = (wn * 32 + nip * 16 + jB_row * 8 + l7) * ROWB + jB_col * 16;

    float acc[4][4][4];
#pragma unroll
    for (int i = 0; i < 4; i++)
#pragma unroll
        for (int j = 0; j < 4; j++)
#pragma unroll
            for (int r = 0; r < 4; r++) acc[i][j][r] = 0.0f;

    // per-thread single bulk copy: t<128 -> A row t; else B row t-128
    const int brow = t & 127;
    auto issue_stage = [&](int ks) {
        const int bufi = ks & 1;
        if (t < 128)
            bulk_cp(smb + QKV_A(bufi) + brow * ROWB,
                    g_Xh + (size_t)(m0 + brow) * E_DIM + ks * 64, 128, mbA[bufi]);
        else
            bulk_cp(smb + QKV_B(bufi) + brow * ROWB,
                    W + (size_t)(n0 + brow) * E_DIM + ks * 64, 128, mbA[bufi]);
    };

    if (t == 0) {
        MBAR_INIT(mbA[0], 1); MBAR_INIT(mbA[1], 1);
        MBAR_EXPECT(mbA[0], QKV_STAGE_BYTES);
        MBAR_EXPECT(mbA[1], QKV_STAGE_BYTES);
    }
    __syncthreads();
    issue_stage(0);
    issue_stage(1);

    int ph[2] = { 0, 0 };

    for (int ks = 0; ks < 16; ks++) {
        const int bufi = ks & 1;
        mbar_wait(mbA[bufi], (unsigned)ph[bufi]);
        ph[bufi] ^= 1;

        const unsigned Ab = smb + QKV_A(bufi);
        const unsigned Bb = smb + QKV_B(bufi);
#pragma unroll
        for (int kk = 0; kk < 4; kk++) {
            const unsigned kbb = kk * 32;
            unsigned af[4][4];
#pragma unroll
            for (int mi = 0; mi < 4; mi++)
                ldsm4(af[mi], Ab + aoff[mi] + kbb);
            unsigned bfp[2][4];
#pragma unroll
            for (int nip = 0; nip < 2; nip++)
                ldsm4(bfp[nip], Bb + boff[nip] + kbb);
#pragma unroll
            for (int mi = 0; mi < 4; mi++)
#pragma unroll
                for (int nip = 0; nip < 2; nip++) {
                    mma_f16(acc[mi][2 * nip],     af[mi][0], af[mi][1], af[mi][2], af[mi][3],
                            bfp[nip][0], bfp[nip][1]);
                    mma_f16(acc[mi][2 * nip + 1], af[mi][0], af[mi][1], af[mi][2], af[mi][3],
                            bfp[nip][2], bfp[nip][3]);
                }
        }

        if (ks + 2 < 16) {
            if (t == 0) MBAR_EXPECT(mbA[bufi], QKV_STAGE_BYTES);
            __syncthreads();           // all warps done reading buf; expect posted
            issue_stage(ks + 2);
        }
    }

#pragma unroll
    for (int mi = 0; mi < 4; mi++) {
#pragma unroll
        for (int ni = 0; ni < 4; ni++) {
            int row = m0 + wm * 64 + mi * 16 + lr;
            int col = n0 + wn * 32 + ni * 8 + 2 * lc;
            *(__half2*)&C[(size_t)row * E_DIM + col] =
                __floats2half2_rn(acc[mi][ni][0], acc[mi][ni][1]);
            *(__half2*)&C[(size_t)(row + 8) * E_DIM + col] =
                __floats2half2_rn(acc[mi][ni][2], acc[mi][ni][3]);
        }
    }
}

// ---------------------------------------------------------------------------
// Kernel 2: per-head L2 norm (fp16 in, fp32 math), fold g into Q, fp16 out.
// ---------------------------------------------------------------------------
__global__ __launch_bounds__(256) void norm_heads(const float* __restrict__ gptr)
{
    int warp = (blockIdx.x * blockDim.x + threadIdx.x) >> 5;
    int lane = threadIdx.x & 31;
    const int total = M_TOT * H_NUM;
    if (warp >= total) return;

    const __half* src = (blockIdx.y == 0) ? g_Qr : g_Kr;
    __half*       dst = (blockIdx.y == 0) ? g_Qh : g_Kh;
    float         sc  = (blockIdx.y == 0) ? *gptr : 1.0f;

    __half2 v = ((const __half2*)(src + (size_t)warp * 64))[lane];
    float2 vf = __half22float2(v);
    float ss = vf.x * vf.x + vf.y * vf.y;
#pragma unroll
    for (int m = 16; m > 0; m >>= 1) ss += __shfl_xor_sync(0xffffffffu, ss, m);
    float inv = sc / fmaxf(sqrtf(ss), 1e-12f);
    ((__half2*)(dst + (size_t)warp * 64))[lane] = __floats2half2_rn(vf.x * inv, vf.y * inv);
}

// ---------------------------------------------------------------------------
// Kernel 3: V transpose fp16->fp16: g_Vh [b*2048+s][f] -> g_Vt [(b*E+f)][s].
// ---------------------------------------------------------------------------
__global__ __launch_bounds__(256) void transpose_v()
{
    __shared__ __half tile[32][66];
    const int s0 = blockIdx.x * 32;
    const int f0 = blockIdx.y * 64;
    const int b  = blockIdx.z;
    const int tx = threadIdx.x;      // 0..31
    const int ty = threadIdx.y;      // 0..7
    const int tid = ty * 32 + tx;

#pragma unroll
    for (int j = 0; j < 4; j++) {
        int r = ty + 8 * j;
        *(__half2*)&tile[r][2 * tx] =
            *(const __half2*)&g_Vh[(size_t)(b * S_LEN + s0 + r) * E_DIM + f0 + 2 * tx];
    }
    __syncthreads();

    const int f  = tid >> 2;
    const int sp0 = (tid & 3) * 4;
#pragma unroll
    for (int k = 0; k < 4; k++) {
        int sp = sp0 + k;
        __half2 v = __halves2half2(tile[2 * sp][f], tile[2 * sp + 1][f]);
        *(__half2*)&g_Vt[(size_t)(b * E_DIM + f0 + f) * S_LEN + s0 + 2 * sp] = v;
    }
}

// ---------------------------------------------------------------------------
// Kernel 4: flash attention, fp16 MMA + ldmatrix. Br=128, Bc=64, P fully
// register-resident. K/V staged via cp.async.bulk into a 4-buffer ring,
// 2 tiles per mbarrier pair, ONE __syncthreads per 2 tiles. No M0 shift
// (exp(s) directly -- constant cancels in normalization).
// ---------------------------------------------------------------------------
#define AT_Q    64                              // Q tile byte offset
#define AT_QB   (128 * ROWB)                    // 18432
#define AT_K(buf) (64 + AT_QB + (buf) * (64 * ROWB))
#define AT_V(buf) (64 + AT_QB + 4 * 64 * ROWB + (buf) * (64 * ROWB))
#define AT_PAIR_BYTES 32768u                    // 2 tiles x (K 8KB + V 8KB)
#define ATTN_SMEM (64 + AT_QB + 8 * 64 * ROWB)  // 92224 B

__global__ __launch_bounds__(256, 2) void attn_kernel(float* __restrict__ out)
{
    extern __shared__ __align__(16) char smc[];
    const unsigned smb = (unsigned)__cvta_generic_to_shared(smc);
    const unsigned mbA[2] = { smb, smb + 8 };
    __half* Qs = (__half*)(smc + AT_Q);

    const int b     = blockIdx.z;
    const int h     = blockIdx.y;
    const int q0    = blockIdx.x * 128;
    const int t     = threadIdx.x;
    const int warp  = t >> 5;
    const int lane  = t & 31;
    const int lr    = lane >> 2;
    const int lc    = lane & 3;
    const int r0    = warp * 16;

    const int l7 = lane & 7;
    const int jA_row = (lane >> 3) & 1;
    const int jA_col = (lane >> 4) & 1;
    const int jB_row = (lane >> 4) & 1;
    const int jB_col = (lane >> 3) & 1;

    const unsigned aoff = (r0 + jA_row * 8 + l7) * ROWB + jA_col * 16;
    unsigned noff[4];
#pragma unroll
    for (int np = 0; np < 4; np++)
        noff[np] = (np * 16 + jB_row * 8 + l7) * ROWB + jB_col * 16;

    const __half* Qg  = g_Qh + ((size_t)(b * S_LEN) + q0) * E_DIM + h * D_HEAD;
    const __half* Kg  = g_Kh + (size_t)(b * S_LEN) * E_DIM + h * D_HEAD;
    const __half* Vtg = g_Vt + (size_t)(b * E_DIM + h * D_HEAD) * S_LEN;

    // per-thread single bulk copy per pair:
    // bit7 of t: tile within pair; bit6: K vs V; bits 0..5: row.
    const int prow  = t & 63;
    const int ptile = (t >> 7) & 1;
    const int pisv  = (t >> 6) & 1;
    auto issue_pair = [&](int p) {
        const int kt   = 2 * p + ptile;
        const int bufi = kt & 3;
        if (!pisv)
            bulk_cp(smb + AT_K(bufi) + prow * ROWB,
                    Kg + (size_t)(kt * 64 + prow) * E_DIM, 128, mbA[p & 1]);
        else
            bulk_cp(smb + AT_V(bufi) + prow * ROWB,
                    Vtg + (size_t)prow * S_LEN + kt * 64, 128, mbA[p & 1]);
    };

    if (t == 0) {
        MBAR_INIT(mbA[0], 1); MBAR_INIT(mbA[1], 1);
        MBAR_EXPECT(mbA[0], AT_PAIR_BYTES);
        MBAR_EXPECT(mbA[1], AT_PAIR_BYTES);
    }
    // stage Q tile (128x64 halfs) with plain vector loads
#pragma unroll
    for (int i = 0; i < 4; i++) {
        int s  = t + i * 256;
        int r  = s >> 3;
        int c8 = s & 7;
        *(uint4*)&Qs[r * 72 + c8 * 8] = *(const uint4*)&Qg[(size_t)r * E_DIM + c8 * 8];
    }
    __syncthreads();            // mbar init + Q visible
    issue_pair(0);
    issue_pair(1);

    unsigned qf[4][4];
#pragma unroll
    for (int kk = 0; kk < 4; kk++)
        ldsm4(qf[kk], smb + AT_Q + aoff + kk * 32);

    float oc[8][4];
#pragma unroll
    for (int ni = 0; ni < 8; ni++)
#pragma unroll
        for (int r = 0; r < 4; r++) oc[ni][r] = 0.0f;
    float l0 = 0.0f, l1 = 0.0f;

    int ph[2] = { 0, 0 };

    for (int p = 0; p < 16; p++) {
        const int mbw = p & 1;
        mbar_wait(mbA[mbw], (unsigned)ph[mbw]);
        ph[mbw] ^= 1;

#pragma unroll
        for (int half = 0; half < 2; half++) {
            const int bufi = 2 * mbw + half;   // (2p+half) & 3
            const unsigned Kb = smb + AT_K(bufi);
            const unsigned Vb = smb + AT_V(bufi);

            // ---- S = Q K^T ----
            float sv[8][4];
#pragma unroll
            for (int ni = 0; ni < 8; ni++)
#pragma unroll
                for (int r = 0; r < 4; r++) sv[ni][r] = 0.0f;

#pragma unroll
            for (int kk = 0; kk < 4; kk++) {
                const unsigned kbb = kk * 32;
#pragma unroll
                for (int np = 0; np < 4; np++) {
                    unsigned bfp[4];
                    ldsm4(bfp, Kb + noff[np] + kbb);
                    mma_f16(sv[2 * np],     qf[kk][0], qf[kk][1], qf[kk][2], qf[kk][3],
                            bfp[0], bfp[1]);
                    mma_f16(sv[2 * np + 1], qf[kk][0], qf[kk][1], qf[kk][2], qf[kk][3],
                            bfp[2], bfp[3]);
                }
            }

            // ---- P = exp(S) (no max shift; cancels in normalization) ----
            unsigned pk0[8], pk1[8];
#pragma unroll
            for (int ni = 0; ni < 8; ni++) {
                float p00 = __expf(sv[ni][0]);
                float p01 = __expf(sv[ni][1]);
                float p10 = __expf(sv[ni][2]);
                float p11 = __expf(sv[ni][3]);
                l0 += p00 + p01;
                l1 += p10 + p11;
                pk0[ni] = pack_h2(p00, p01);
                pk1[ni] = pack_h2(p10, p11);
            }

            // ---- O += P @ V (A-frags from registers) ----
#pragma unroll
            for (int j = 0; j < 4; j++) {
                const unsigned kbb = j * 32;
                unsigned a0 = pk0[2 * j],     a1 = pk1[2 * j];
                unsigned a2 = pk0[2 * j + 1], a3 = pk1[2 * j + 1];
#pragma unroll
                for (int np = 0; np < 4; np++) {
                    unsigned bfp[4];
                    ldsm4(bfp, Vb + noff[np] + kbb);
                    mma_f16(oc[2 * np],     a0, a1, a2, a3, bfp[0], bfp[1]);
                    mma_f16(oc[2 * np + 1], a0, a1, a2, a3, bfp[2], bfp[3]);
                }
            }
        }

        if (p + 2 < 16) {
            if (t == 0) MBAR_EXPECT(mbA[mbw], AT_PAIR_BYTES);
            __syncthreads();        // all warps done with these buffers
            issue_pair(p + 2);
        }
    }

    // ---- epilogue: warp-local row sums, normalize, store ----
    l0 += __shfl_xor_sync(0xffffffffu, l0, 1);
    l0 += __shfl_xor_sync(0xffffffffu, l0, 2);
    l1 += __shfl_xor_sync(0xffffffffu, l1, 1);
    l1 += __shfl_xor_sync(0xffffffffu, l1, 2);
    float inv0 = 1.0f / l0;
    float inv1 = 1.0f / l1;

    int ra = q0 + r0 + lr;
#pragma unroll
    for (int ni = 0; ni < 8; ni++) {
        int col = h * D_HEAD + ni * 8 + 2 * lc;
        *(float2*)&out[((size_t)(b * S_LEN) + ra) * E_DIM + col] =
            make_float2(oc[ni][0] * inv0, oc[ni][1] * inv0);
        *(float2*)&out[((size_t)(b * S_LEN) + ra + 8) * E_DIM + col] =
            make_float2(oc[ni][2] * inv1, oc[ni][3] * inv1);
    }
}

// ---------------------------------------------------------------------------
extern "C" void kernel_launch(void* const* d_in, const int* in_sizes, int n_in,
                              void* d_out, int out_size)
{
    const float* x  = (const float*)d_in[0];
    const float* Wq = (const float*)d_in[1];
    const float* Wk = (const float*)d_in[2];
    const float* Wv = (const float*)d_in[3];
    const float* g  = (const float*)d_in[4];
    float* out = (float*)d_out;

    // 0) fp32 -> fp16 conversion of all GEMM inputs (single launch)
    cvt_all<<<(NCVT + 255) / 256, 256>>>(x, Wq, Wk, Wv);

    // 1) QKV projections (fp16 MMA + ldmatrix, cp.async.bulk staging)
    {
        cudaFuncSetAttribute(qkv_gemm, cudaFuncAttributeMaxDynamicSharedMemorySize,
                             QKV_SMEM);
        dim3 grid(E_DIM / 128, M_TOT / 128, 3);
        qkv_gemm<<<grid, 256, QKV_SMEM>>>();
    }

    // 2) per-head L2 norm -> fp16 Q/K (g folded into Q)
    {
        const int chunks = M_TOT * H_NUM;
        dim3 ngrid(chunks / 8, 2);
        norm_heads<<<ngrid, 256>>>(g);
    }

    // 3) V transpose (fp16 -> fp16)
    {
        dim3 tgrid(S_LEN / 32, E_DIM / 64, B_NUM);
        dim3 tblk(32, 8);
        transpose_v<<<tgrid, tblk>>>();
    }

    // 4) Flash attention (bulk staging, 4-buffer ring, 1 sync per 2 tiles)
    {
        cudaFuncSetAttribute(attn_kernel, cudaFuncAttributeMaxDynamicSharedMemorySize,
                             ATTN_SMEM);
        dim3 agrid(S_LEN / 128, H_NUM, B_NUM);
        attn_kernel<<<agrid, 256, ATTN_SMEM>>>(out);
    }
}

// round 16
// speedup vs baseline: 1.7728x; 1.7728x over previous
#include <cuda_runtime.h>
#include <cuda_fp16.h>
#include <math.h>

#define S_LEN  2048
#define E_DIM  1024
#define H_NUM  16
#define D_HEAD 64
#define B_NUM  2
#define M_TOT  (B_NUM * S_LEN)   // 4096

// ---------------- device scratch (all fp16 intermediates) ----------------
__device__ __half g_Xh[(size_t)M_TOT * E_DIM];    // fp16 x
__device__ __half g_Wqh[(size_t)E_DIM * E_DIM];
__device__ __half g_Wkh[(size_t)E_DIM * E_DIM];
__device__ __half g_Wvh[(size_t)E_DIM * E_DIM];
__device__ __half g_Qr[(size_t)M_TOT * E_DIM];    // raw fp16 projections
__device__ __half g_Kr[(size_t)M_TOT * E_DIM];
__device__ __half g_Vh[(size_t)M_TOT * E_DIM];
// blocked + swizzled per-head layouts for bulk staging:
__device__ __half g_Qb[(size_t)M_TOT * E_DIM];    // [(b*16+h)][s][64] swz rows
__device__ __half g_Kb[(size_t)M_TOT * E_DIM];    // [(b*16+h)][s][64] swz rows
__device__ __half g_Vtb[(size_t)M_TOT * E_DIM];   // [(b*16+h)][kt][d][64] swz rows

// ---------------- helpers ----------------
__device__ __forceinline__ void mma_f16(float c[4],
                                        unsigned a0, unsigned a1, unsigned a2, unsigned a3,
                                        unsigned b0, unsigned b1) {
    asm volatile(
        "mma.sync.aligned.m16n8k16.row.col.f32.f16.f16.f32 "
        "{%0,%1,%2,%3}, {%4,%5,%6,%7}, {%8,%9}, {%0,%1,%2,%3};"
        : "+f"(c[0]), "+f"(c[1]), "+f"(c[2]), "+f"(c[3])
        : "r"(a0), "r"(a1), "r"(a2), "r"(a3), "r"(b0), "r"(b1));
}

__device__ __forceinline__ void ldsm4(unsigned r[4], unsigned addr) {
    asm volatile("ldmatrix.sync.aligned.m8n8.x4.shared.b16 {%0,%1,%2,%3}, [%4];"
                 : "=r"(r[0]), "=r"(r[1]), "=r"(r[2]), "=r"(r[3]) : "r"(addr));
}

__device__ __forceinline__ void cp16(void* smem_dst, const void* gmem_src) {
    unsigned s = (unsigned)__cvta_generic_to_shared(smem_dst);
    asm volatile("cp.async.cg.shared.global [%0], [%1], 16;" :: "r"(s), "l"(gmem_src));
}
#define CP_COMMIT() asm volatile("cp.async.commit_group;")
#define CP_WAIT0()  asm volatile("cp.async.wait_group 0;")

__device__ __forceinline__ unsigned pack_h2(float a, float b) {
    __half2 h = __floats2half2_rn(a, b);
    return *(unsigned*)&h;
}

__device__ __forceinline__ void bulk_cp(unsigned smem_dst, const void* gmem_src,
                                        unsigned bytes, unsigned mbar) {
    asm volatile(
        "cp.async.bulk.shared::cta.global.mbarrier::complete_tx::bytes "
        "[%0], [%1], %2, [%3];"
        :: "r"(smem_dst), "l"(gmem_src), "r"(bytes), "r"(mbar) : "memory");
}

#define MBAR_INIT(addr, cnt) \
    asm volatile("mbarrier.init.shared.b64 [%0], %1;" :: "r"(addr), "r"(cnt) : "memory")
#define MBAR_EXPECT(addr, bytes) \
    asm volatile("mbarrier.arrive.expect_tx.shared.b64 _, [%0], %1;" \
                 :: "r"(addr), "r"(bytes) : "memory")

__device__ __forceinline__ void mbar_wait(unsigned addr, unsigned parity) {
    asm volatile(
        "{\n\t"
        ".reg .pred P1;\n\t"
        "WAIT_LOOP_%=:\n\t"
        "mbarrier.try_wait.parity.acquire.cta.shared::cta.b64 P1, [%0], %1, 0x989680;\n\t"
        "@P1 bra.uni WAIT_DONE_%=;\n\t"
        "bra.uni WAIT_LOOP_%=;\n\t"
        "WAIT_DONE_%=:\n\t"
        "}"
        :: "r"(addr), "r"(parity) : "memory");
}

// ---------------------------------------------------------------------------
// Kernel 0: one-shot fp32 -> fp16 conversion for x, Wq, Wk, Wv.
// ---------------------------------------------------------------------------
#define NX4 (M_TOT * E_DIM / 4)     // 1048576
#define NW4 (E_DIM * E_DIM / 4)     // 262144
#define NCVT (NX4 + 3 * NW4)        // 1835008

__global__ void cvt_all(const float* __restrict__ x,  const float* __restrict__ wq,
                        const float* __restrict__ wk, const float* __restrict__ wv)
{
    int i = blockIdx.x * blockDim.x + threadIdx.x;
    if (i >= NCVT) return;
    const float* src;
    __half* dst;
    int j;
    if (i < NX4)                  { src = x;  dst = g_Xh;  j = i; }
    else if (i < NX4 + NW4)       { src = wq; dst = g_Wqh; j = i - NX4; }
    else if (i < NX4 + 2 * NW4)   { src = wk; dst = g_Wkh; j = i - NX4 - NW4; }
    else                          { src = wv; dst = g_Wvh; j = i - NX4 - 2 * NW4; }
    float4 v = ((const float4*)src)[j];
    __half2* d = (__half2*)dst;
    d[2 * j]     = __floats2half2_rn(v.x, v.y);
    d[2 * j + 1] = __floats2half2_rn(v.z, v.w);
}

// ---------------------------------------------------------------------------
// Kernel 1: C = x @ W^T, m16n8k16 fp16 MMA + ldmatrix, BK=64, cp.async staging
// (R14-proven). Stride 72 halfs => conflict-free.
// ---------------------------------------------------------------------------
#define ASH (128 * 72)
#define QKV_SMEM ((size_t)4 * ASH * sizeof(__half))   // 73728 B

__global__ __launch_bounds__(256, 2) void qkv_gemm()
{
    extern __shared__ __half smh[];
    const unsigned smbase = (unsigned)__cvta_generic_to_shared(smh);
    const unsigned Abase[2] = { smbase,                smbase + ASH * 2 };
    const unsigned Bbase[2] = { smbase + 2 * ASH * 2,  smbase + 3 * ASH * 2 };
    __half* As[2] = { smh,           smh + ASH };
    __half* Bs[2] = { smh + 2*ASH,   smh + 3*ASH };

    const int z  = blockIdx.z;
    const __half* W = (z == 0) ? g_Wqh : (z == 1) ? g_Wkh : g_Wvh;
    __half*       C = (z == 0) ? g_Qr  : (z == 1) ? g_Kr  : g_Vh;

    const int m0   = blockIdx.y * 128;
    const int n0   = blockIdx.x * 128;
    const int t    = threadIdx.x;
    const int warp = t >> 5;
    const int lane = t & 31;
    const int wm   = warp >> 2;
    const int wn   = warp & 3;
    const int lr   = lane >> 2;
    const int lc   = lane & 3;

    const int l7 = lane & 7;
    const int jA_row = (lane >> 3) & 1;
    const int jA_col = (lane >> 4) & 1;
    const int jB_row = (lane >> 4) & 1;
    const int jB_col = (lane >> 3) & 1;

    unsigned aoff[4], boff[2];
#pragma unroll
    for (int mi = 0; mi < 4; mi++)
        aoff[mi] = ((wm * 64 + mi * 16 + jA_row * 8 + l7) * 72 + jA_col * 8) * 2;
#pragma unroll
    for (int nip = 0; nip < 2; nip++)
        boff[nip] = ((wn * 32 + nip * 16 + jB_row * 8 + l7) * 72 + jB_col * 8) * 2;

    float acc[4][4][4];
#pragma unroll
    for (int i = 0; i < 4; i++)
#pragma unroll
        for (int j = 0; j < 4; j++)
#pragma unroll
            for (int r = 0; r < 4; r++) acc[i][j][r] = 0.0f;

    auto prefetch = [&](int ks, int buf) {
        const int k0 = ks * 64;
#pragma unroll
        for (int i = 0; i < 4; i++) {
            int s   = t + i * 256;
            int row = s >> 3;
            int c8  = s & 7;
            cp16(&As[buf][row * 72 + c8 * 8], &g_Xh[(size_t)(m0 + row) * E_DIM + k0 + c8 * 8]);
            cp16(&Bs[buf][row * 72 + c8 * 8], &W   [(size_t)(n0 + row) * E_DIM + k0 + c8 * 8]);
        }
    };

    prefetch(0, 0); CP_COMMIT();
    int buf = 0;

    for (int ks = 0; ks < 16; ks++) {
        CP_WAIT0();
        __syncthreads();
        if (ks + 1 < 16) { prefetch(ks + 1, buf ^ 1); CP_COMMIT(); }

#pragma unroll
        for (int kk = 0; kk < 4; kk++) {
            const unsigned kbb = kk * 32;
            unsigned af[4][4];
#pragma unroll
            for (int mi = 0; mi < 4; mi++)
                ldsm4(af[mi], Abase[buf] + aoff[mi] + kbb);
            unsigned bfp[2][4];
#pragma unroll
            for (int nip = 0; nip < 2; nip++)
                ldsm4(bfp[nip], Bbase[buf] + boff[nip] + kbb);
#pragma unroll
            for (int mi = 0; mi < 4; mi++)
#pragma unroll
                for (int nip = 0; nip < 2; nip++) {
                    mma_f16(acc[mi][2 * nip],     af[mi][0], af[mi][1], af[mi][2], af[mi][3],
                            bfp[nip][0], bfp[nip][1]);
                    mma_f16(acc[mi][2 * nip + 1], af[mi][0], af[mi][1], af[mi][2], af[mi][3],
                            bfp[nip][2], bfp[nip][3]);
                }
        }
        buf ^= 1;
    }

#pragma unroll
    for (int mi = 0; mi < 4; mi++) {
#pragma unroll
        for (int ni = 0; ni < 4; ni++) {
            int row = m0 + wm * 64 + mi * 16 + lr;
            int col = n0 + wn * 32 + ni * 8 + 2 * lc;
            *(__half2*)&C[(size_t)row * E_DIM + col] =
                __floats2half2_rn(acc[mi][ni][0], acc[mi][ni][1]);
            *(__half2*)&C[(size_t)(row + 8) * E_DIM + col] =
                __floats2half2_rn(acc[mi][ni][2], acc[mi][ni][3]);
        }
    }
}

// ---------------------------------------------------------------------------
// Kernel 2: per-head L2 norm; write BLOCKED + SWIZZLED per-head Q/K.
// dst[(b*16+h)][s][64] with 16B-chunk index ^= (s & 7).
// ---------------------------------------------------------------------------
__global__ __launch_bounds__(256) void norm_heads(const float* __restrict__ gptr)
{
    int warp = (blockIdx.x * blockDim.x + threadIdx.x) >> 5;
    int lane = threadIdx.x & 31;
    const int total = M_TOT * H_NUM;
    if (warp >= total) return;

    const __half* src = (blockIdx.y == 0) ? g_Qr : g_Kr;
    __half*       dst = (blockIdx.y == 0) ? g_Qb : g_Kb;
    float         sc  = (blockIdx.y == 0) ? *gptr : 1.0f;

    __half2 v = ((const __half2*)(src + (size_t)warp * 64))[lane];
    float2 vf = __half22float2(v);
    float ss = vf.x * vf.x + vf.y * vf.y;
#pragma unroll
    for (int m = 16; m > 0; m >>= 1) ss += __shfl_xor_sync(0xffffffffu, ss, m);
    float inv = sc / fmaxf(sqrtf(ss), 1e-12f);

    const int h  = warp & 15;
    const int bs = warp >> 4;              // b*S_LEN + s
    const int b  = bs >> 11;
    const int s  = bs & 2047;
    // within-row half2 slot: chunk = lane>>2 (8 halfs per 16B), swizzled by s&7
    const int wchunk = (lane >> 2) ^ (s & 7);
    size_t base = ((size_t)(b * H_NUM + h) * S_LEN + s) * 64;
    *(__half2*)&dst[base + wchunk * 8 + (lane & 3) * 2] =
        __floats2half2_rn(vf.x * inv, vf.y * inv);
}

// ---------------------------------------------------------------------------
// Kernel 3: V transpose -> BLOCKED + SWIZZLED per-head per-ktile V^T.
// dst[(b*16+h)][kt][d][64 s] 8KB blocks, chunk ^= (d & 7).
// blockIdx.y == head (64 f cols == one head's d range).
// ---------------------------------------------------------------------------
__global__ __launch_bounds__(256) void transpose_v()
{
    __shared__ __half tile[32][66];
    const int s0 = blockIdx.x * 32;
    const int h  = blockIdx.y;
    const int b  = blockIdx.z;
    const int tx = threadIdx.x;
    const int ty = threadIdx.y;
    const int tid = ty * 32 + tx;

#pragma unroll
    for (int j = 0; j < 4; j++) {
        int r = ty + 8 * j;
        *(__half2*)&tile[r][2 * tx] =
            *(const __half2*)&g_Vh[(size_t)(b * S_LEN + s0 + r) * E_DIM + h * 64 + 2 * tx];
    }
    __syncthreads();

    const int d   = tid >> 2;        // 0..63
    const int sp0 = (tid & 3) * 4;
    const int kt  = s0 >> 6;
    size_t base = ((size_t)(b * H_NUM + h) * 32 + kt) * 4096 + (size_t)d * 64;
#pragma unroll
    for (int k = 0; k < 4; k++) {
        int sp = sp0 + k;                        // s-pair index 0..15 within 32-s block
        int sb = (s0 & 63) + 2 * sp;             // s within 64-tile (even)
        int byte = sb * 2;                       // byte offset within 128B row
        int wchunk = (byte >> 4) ^ (d & 7);
        __half2 v = __halves2half2(tile[2 * sp][d], tile[2 * sp + 1][d]);
        *(__half2*)&g_Vtb[base + wchunk * 8 + ((byte & 15) >> 1)] = v;
    }
}

// ---------------------------------------------------------------------------
// Kernel 4: flash attention. Br=128, Bc=64, P register-resident. K/V tiles
// are single 8KB cp.async.bulk copies (gmem pre-swizzled), 4-buffer ring,
// one __syncthreads per 2 tiles. ldmatrix uses XOR-swizzled addressing.
// ---------------------------------------------------------------------------
#define AT_Q     64                              // Q tile byte offset
#define AT_QB    16384                            // 128 rows x 128B
#define AT_K(buf) (64 + AT_QB + (buf) * 8192)
#define AT_V(buf) (64 + AT_QB + 4 * 8192 + (buf) * 8192)
#define AT_PAIR_BYTES 32768u
#define ATTN_SMEM (64 + AT_QB + 8 * 8192)         // 81984 B

__global__ __launch_bounds__(256, 2) void attn_kernel(float* __restrict__ out)
{
    extern __shared__ __align__(16) char smc[];
    const unsigned smb = (unsigned)__cvta_generic_to_shared(smc);
    const unsigned mbA[2] = { smb, smb + 8 };

    const int b     = blockIdx.z;
    const int h     = blockIdx.y;
    const int q0    = blockIdx.x * 128;
    const int t     = threadIdx.x;
    const int warp  = t >> 5;
    const int lane  = t & 31;
    const int lr    = lane >> 2;
    const int lc    = lane & 3;
    const int r0    = warp * 16;

    const int l7 = lane & 7;
    const int jA_row = (lane >> 3) & 1;
    const int jA_col = (lane >> 4) & 1;
    const int jB_row = (lane >> 4) & 1;
    const int jB_col = (lane >> 3) & 1;

    // A-frag (Q): row in 0..127, 128B rows, swizzled chunks
    const int rowA = r0 + jA_row * 8 + l7;
    const unsigned aRow = (unsigned)rowA * 128;
    const unsigned aSwz = (unsigned)(rowA & 7) << 4;
    const unsigned aCb  = (unsigned)jA_col * 16;
    // B-frags (K rows = s', Vt rows = d): rows 0..63
    unsigned nRow[4], nSwz[4];
#pragma unroll
    for (int np = 0; np < 4; np++) {
        int row = np * 16 + jB_row * 8 + l7;
        nRow[np] = (unsigned)row * 128;
        nSwz[np] = (unsigned)(row & 7) << 4;
    }
    const unsigned nCb = (unsigned)jB_col * 16;

    const size_t head = (size_t)(b * H_NUM + h);
    const __half* Qblk = g_Qb  + (head * S_LEN + q0) * 64;
    const __half* Kblk = g_Kb  + head * S_LEN * 64;
    const __half* Vblk = g_Vtb + head * S_LEN * 64;

    auto issue_pair = [&](int p) {
        // thread 0 only: 4 bulk copies of 8KB
#pragma unroll
        for (int j = 0; j < 2; j++) {
            const int kt   = 2 * p + j;
            const int bufi = kt & 3;
            bulk_cp(smb + AT_K(bufi), Kblk + (size_t)kt * 4096, 8192, mbA[p & 1]);
            bulk_cp(smb + AT_V(bufi), Vblk + (size_t)kt * 4096, 8192, mbA[p & 1]);
        }
    };

    if (t == 0) {
        MBAR_INIT(mbA[0], 1); MBAR_INIT(mbA[1], 1);
        MBAR_EXPECT(mbA[0], AT_PAIR_BYTES);
        MBAR_EXPECT(mbA[1], AT_PAIR_BYTES);
    }
    // Q tile: linear 16KB copy (gmem already swizzled/blocked)
#pragma unroll
    for (int i = 0; i < 4; i++) {
        int s = t + i * 256;             // 0..1023 16B chunks
        *(uint4*)(smc + AT_Q + s * 16) = *(const uint4*)(Qblk + s * 8);
    }
    __syncthreads();            // mbar init + Q visible
    if (t == 0) { issue_pair(0); issue_pair(1); }

    unsigned qf[4][4];
#pragma unroll
    for (int kk = 0; kk < 4; kk++)
        ldsm4(qf[kk], smb + AT_Q + aRow + ((aCb + kk * 32) ^ aSwz));

    float oc[8][4];
#pragma unroll
    for (int ni = 0; ni < 8; ni++)
#pragma unroll
        for (int r = 0; r < 4; r++) oc[ni][r] = 0.0f;
    float l0 = 0.0f, l1 = 0.0f;

    int ph[2] = { 0, 0 };

    for (int p = 0; p < 16; p++) {
        const int mbw = p & 1;
        mbar_wait(mbA[mbw], (unsigned)ph[mbw]);
        ph[mbw] ^= 1;

#pragma unroll
        for (int half = 0; half < 2; half++) {
            const int bufi = 2 * mbw + half;
            const unsigned Kb = smb + AT_K(bufi);
            const unsigned Vb = smb + AT_V(bufi);

            // ---- S = Q K^T ----
            float sv[8][4];
#pragma unroll
            for (int ni = 0; ni < 8; ni++)
#pragma unroll
                for (int r = 0; r < 4; r++) sv[ni][r] = 0.0f;

#pragma unroll
            for (int kk = 0; kk < 4; kk++) {
                const unsigned kbb = nCb + kk * 32;
#pragma unroll
                for (int np = 0; np < 4; np++) {
                    unsigned bfp[4];
                    ldsm4(bfp, Kb + nRow[np] + (kbb ^ nSwz[np]));
                    mma_f16(sv[2 * np],     qf[kk][0], qf[kk][1], qf[kk][2], qf[kk][3],
                            bfp[0], bfp[1]);
                    mma_f16(sv[2 * np + 1], qf[kk][0], qf[kk][1], qf[kk][2], qf[kk][3],
                            bfp[2], bfp[3]);
                }
            }

            // ---- P = exp(S) ----
            unsigned pk0[8], pk1[8];
#pragma unroll
            for (int ni = 0; ni < 8; ni++) {
                float p00 = __expf(sv[ni][0]);
                float p01 = __expf(sv[ni][1]);
                float p10 = __expf(sv[ni][2]);
                float p11 = __expf(sv[ni][3]);
                l0 += p00 + p01;
                l1 += p10 + p11;
                pk0[ni] = pack_h2(p00, p01);
                pk1[ni] = pack_h2(p10, p11);
            }

            // ---- O += P @ V ----
#pragma unroll
            for (int j = 0; j < 4; j++) {
                const unsigned kbb = nCb + j * 32;
                unsigned a0 = pk0[2 * j],     a1 = pk1[2 * j];
                unsigned a2 = pk0[2 * j + 1], a3 = pk1[2 * j + 1];
#pragma unroll
                for (int np = 0; np < 4; np++) {
                    unsigned bfp[4];
                    ldsm4(bfp, Vb + nRow[np] + (kbb ^ nSwz[np]));
                    mma_f16(oc[2 * np],     a0, a1, a2, a3, bfp[0], bfp[1]);
                    mma_f16(oc[2 * np + 1], a0, a1, a2, a3, bfp[2], bfp[3]);
                }
            }
        }

        if (p + 2 < 16) {
            if (t == 0) MBAR_EXPECT(mbA[mbw], AT_PAIR_BYTES);
            __syncthreads();
            if (t == 0) issue_pair(p + 2);
        }
    }

    // ---- epilogue ----
    l0 += __shfl_xor_sync(0xffffffffu, l0, 1);
    l0 += __shfl_xor_sync(0xffffffffu, l0, 2);
    l1 += __shfl_xor_sync(0xffffffffu, l1, 1);
    l1 += __shfl_xor_sync(0xffffffffu, l1, 2);
    float inv0 = 1.0f / l0;
    float inv1 = 1.0f / l1;

    int ra = q0 + r0 + lr;
#pragma unroll
    for (int ni = 0; ni < 8; ni++) {
        int col = h * D_HEAD + ni * 8 + 2 * lc;
        *(float2*)&out[((size_t)(b * S_LEN) + ra) * E_DIM + col] =
            make_float2(oc[ni][0] * inv0, oc[ni][1] * inv0);
        *(float2*)&out[((size_t)(b * S_LEN) + ra + 8) * E_DIM + col] =
            make_float2(oc[ni][2] * inv1, oc[ni][3] * inv1);
    }
}

// ---------------------------------------------------------------------------
extern "C" void kernel_launch(void* const* d_in, const int* in_sizes, int n_in,
                              void* d_out, int out_size)
{
    const float* x  = (const float*)d_in[0];
    const float* Wq = (const float*)d_in[1];
    const float* Wk = (const float*)d_in[2];
    const float* Wv = (const float*)d_in[3];
    const float* g  = (const float*)d_in[4];
    float* out = (float*)d_out;

    // 0) fp32 -> fp16 conversion of all GEMM inputs
    cvt_all<<<(NCVT + 255) / 256, 256>>>(x, Wq, Wk, Wv);

    // 1) QKV projections (cp.async staging, R14-proven)
    {
        cudaFuncSetAttribute(qkv_gemm, cudaFuncAttributeMaxDynamicSharedMemorySize,
                             (int)QKV_SMEM);
        dim3 grid(E_DIM / 128, M_TOT / 128, 3);
        qkv_gemm<<<grid, 256, QKV_SMEM>>>();
    }

    // 2) per-head L2 norm -> blocked/swizzled fp16 Q/K
    {
        const int chunks = M_TOT * H_NUM;
        dim3 ngrid(chunks / 8, 2);
        norm_heads<<<ngrid, 256>>>(g);
    }

    // 3) V transpose -> blocked/swizzled per-ktile V^T
    {
        dim3 tgrid(S_LEN / 32, H_NUM, B_NUM);
        dim3 tblk(32, 8);
        transpose_v<<<tgrid, tblk>>>();
    }

    // 4) Flash attention (8KB bulk tiles, 4-buffer ring)
    {
        cudaFuncSetAttribute(attn_kernel, cudaFuncAttributeMaxDynamicSharedMemorySize,
                             ATTN_SMEM);
        dim3 agrid(S_LEN / 128, H_NUM, B_NUM);
        attn_kernel<<<agrid, 256, ATTN_SMEM>>>(out);
    }
}

// round 17
// speedup vs baseline: 2.0213x; 1.1402x over previous
#include <cuda_runtime.h>
#include <cuda_fp16.h>
#include <math.h>

#define S_LEN  2048
#define E_DIM  1024
#define H_NUM  16
#define D_HEAD 64
#define B_NUM  2
#define M_TOT  (B_NUM * S_LEN)   // 4096

// ---------------- device scratch ----------------
// blocked + swizzled GEMM inputs: [tile][ks][row 128][64 halfs], 16KB blocks
__device__ __half g_Xb[(size_t)M_TOT * E_DIM];    // 32 mtiles x 16 ks
__device__ __half g_Wqb[(size_t)E_DIM * E_DIM];   // 8 ntiles x 16 ks
__device__ __half g_Wkb[(size_t)E_DIM * E_DIM];
__device__ __half g_Wvb[(size_t)E_DIM * E_DIM];
__device__ __half g_Qr[(size_t)M_TOT * E_DIM];    // raw fp16 projections (row-major)
__device__ __half g_Kr[(size_t)M_TOT * E_DIM];
__device__ __half g_Vh[(size_t)M_TOT * E_DIM];
// blocked + swizzled per-head layouts for attention bulk staging:
__device__ __half g_Qb[(size_t)M_TOT * E_DIM];    // [(b*16+h)][s][64] swz rows
__device__ __half g_Kb[(size_t)M_TOT * E_DIM];
__device__ __half g_Vtb[(size_t)M_TOT * E_DIM];   // [(b*16+h)][kt][d][64] swz rows

// ---------------- helpers ----------------
__device__ __forceinline__ void mma_f16(float c[4],
                                        unsigned a0, unsigned a1, unsigned a2, unsigned a3,
                                        unsigned b0, unsigned b1) {
    asm volatile(
        "mma.sync.aligned.m16n8k16.row.col.f32.f16.f16.f32 "
        "{%0,%1,%2,%3}, {%4,%5,%6,%7}, {%8,%9}, {%0,%1,%2,%3};"
        : "+f"(c[0]), "+f"(c[1]), "+f"(c[2]), "+f"(c[3])
        : "r"(a0), "r"(a1), "r"(a2), "r"(a3), "r"(b0), "r"(b1));
}

__device__ __forceinline__ void ldsm4(unsigned r[4], unsigned addr) {
    asm volatile("ldmatrix.sync.aligned.m8n8.x4.shared.b16 {%0,%1,%2,%3}, [%4];"
                 : "=r"(r[0]), "=r"(r[1]), "=r"(r[2]), "=r"(r[3]) : "r"(addr));
}

__device__ __forceinline__ unsigned pack_h2(float a, float b) {
    __half2 h = __floats2half2_rn(a, b);
    return *(unsigned*)&h;
}

__device__ __forceinline__ void bulk_cp(unsigned smem_dst, const void* gmem_src,
                                        unsigned bytes, unsigned mbar) {
    asm volatile(
        "cp.async.bulk.shared::cta.global.mbarrier::complete_tx::bytes "
        "[%0], [%1], %2, [%3];"
        :: "r"(smem_dst), "l"(gmem_src), "r"(bytes), "r"(mbar) : "memory");
}

#define MBAR_INIT(addr, cnt) \
    asm volatile("mbarrier.init.shared.b64 [%0], %1;" :: "r"(addr), "r"(cnt) : "memory")
#define MBAR_EXPECT(addr, bytes) \
    asm volatile("mbarrier.arrive.expect_tx.shared.b64 _, [%0], %1;" \
                 :: "r"(addr), "r"(bytes) : "memory")

__device__ __forceinline__ void mbar_wait(unsigned addr, unsigned parity) {
    asm volatile(
        "{\n\t"
        ".reg .pred P1;\n\t"
        "WAIT_LOOP_%=:\n\t"
        "mbarrier.try_wait.parity.acquire.cta.shared::cta.b64 P1, [%0], %1, 0x989680;\n\t"
        "@P1 bra.uni WAIT_DONE_%=;\n\t"
        "bra.uni WAIT_LOOP_%=;\n\t"
        "WAIT_DONE_%=:\n\t"
        "}"
        :: "r"(addr), "r"(parity) : "memory");
}

#define ONE2 0x3C003C00u   // half2(1.0, 1.0)

// ---------------------------------------------------------------------------
// Kernel 0: fp32 -> fp16 + blocked/swizzled layout for x, Wq, Wk, Wv.
// One thread = 8 consecutive floats = one 16B output chunk.
// dst chunk: block (t16 = rowtile*16+ks) * 8192 halfs + row*64 + (ch^(row&7))*8
// ---------------------------------------------------------------------------
#define NX8 (M_TOT * E_DIM / 8)     // 524288
#define NW8 (E_DIM * E_DIM / 8)     // 131072
#define NCVT8 (NX8 + 3 * NW8)       // 917504

__global__ void cvt_all(const float* __restrict__ x,  const float* __restrict__ wq,
                        const float* __restrict__ wk, const float* __restrict__ wv)
{
    int i = blockIdx.x * blockDim.x + threadIdx.x;
    if (i >= NCVT8) return;
    const float* src;
    __half* dst;
    int c;
    if (i < NX8)                  { src = x;  dst = g_Xb;  c = i; }
    else if (i < NX8 + NW8)       { src = wq; dst = g_Wqb; c = i - NX8; }
    else if (i < NX8 + 2 * NW8)   { src = wk; dst = g_Wkb; c = i - NX8 - NW8; }
    else                          { src = wv; dst = g_Wvb; c = i - NX8 - 2 * NW8; }

    const int m   = c >> 7;          // row in source (128 chunks per 1024-k row)
    const int kc8 = c & 127;         // 8-float chunk along k
    float4 v0 = ((const float4*)src)[c * 2];
    float4 v1 = ((const float4*)src)[c * 2 + 1];

    const int mt  = m >> 7;
    const int row = m & 127;
    const int ks  = kc8 >> 3;        // 64-k stage
    const int ch  = (kc8 & 7) ^ (row & 7);
    size_t off = ((size_t)(mt * 16 + ks) * 128 + row) * 64 + ch * 8;

    __half2 h[4];
    h[0] = __floats2half2_rn(v0.x, v0.y);
    h[1] = __floats2half2_rn(v0.z, v0.w);
    h[2] = __floats2half2_rn(v1.x, v1.y);
    h[3] = __floats2half2_rn(v1.z, v1.w);
    *(uint4*)&dst[off] = *(uint4*)h;
}

// ---------------------------------------------------------------------------
// Kernel 1: C = x @ W^T, m16n8k16 fp16 MMA + ldmatrix, BK=64. Staging via
// 16KB cp.async.bulk per matrix per stage (gmem pre-blocked/swizzled).
// ---------------------------------------------------------------------------
#define QG_A(buf) (64 + (buf) * 32768)
#define QG_B(buf) (64 + (buf) * 32768 + 16384)
#define QG_STAGE_BYTES 32768u
#define QKV_SMEM (64 + 65536)        // 65600 B

__global__ __launch_bounds__(256, 2) void qkv_gemm()
{
    extern __shared__ __align__(16) char smc[];
    const unsigned smb = (unsigned)__cvta_generic_to_shared(smc);
    const unsigned mbA[2] = { smb, smb + 8 };

    const int z  = blockIdx.z;
    const __half* Wb = (z == 0) ? g_Wqb : (z == 1) ? g_Wkb : g_Wvb;
    __half*       C  = (z == 0) ? g_Qr  : (z == 1) ? g_Kr  : g_Vh;

    const int mt   = blockIdx.y;
    const int nt   = blockIdx.x;
    const int m0   = mt * 128;
    const int n0   = nt * 128;
    const int t    = threadIdx.x;
    const int warp = t >> 5;
    const int lane = t & 31;
    const int wm   = warp >> 2;
    const int wn   = warp & 3;
    const int lr   = lane >> 2;
    const int lc   = lane & 3;

    const int l7 = lane & 7;
    const int jA_row = (lane >> 3) & 1;
    const int jA_col = (lane >> 4) & 1;
    const int jB_row = (lane >> 4) & 1;
    const int jB_col = (lane >> 3) & 1;

    unsigned aRow[4], aSwz[4];
#pragma unroll
    for (int mi = 0; mi < 4; mi++) {
        int row = wm * 64 + mi * 16 + jA_row * 8 + l7;
        aRow[mi] = (unsigned)row * 128;
        aSwz[mi] = (unsigned)(row & 7) << 4;
    }
    unsigned bRow[2], bSwz[2];
#pragma unroll
    for (int nip = 0; nip < 2; nip++) {
        int row = wn * 32 + nip * 16 + jB_row * 8 + l7;
        bRow[nip] = (unsigned)row * 128;
        bSwz[nip] = (unsigned)(row & 7) << 4;
    }
    const unsigned aCb = (unsigned)jA_col * 16;
    const unsigned bCb = (unsigned)jB_col * 16;

    float acc[4][4][4];
#pragma unroll
    for (int i = 0; i < 4; i++)
#pragma unroll
        for (int j = 0; j < 4; j++)
#pragma unroll
            for (int r = 0; r < 4; r++) acc[i][j][r] = 0.0f;

    auto issue_stage = [&](int ks) {   // thread 0 only
        const int bufi = ks & 1;
        bulk_cp(smb + QG_A(bufi), g_Xb + ((size_t)(mt * 16 + ks)) * 8192, 16384, mbA[bufi]);
        bulk_cp(smb + QG_B(bufi), Wb   + ((size_t)(nt * 16 + ks)) * 8192, 16384, mbA[bufi]);
    };

    if (t == 0) {
        MBAR_INIT(mbA[0], 1); MBAR_INIT(mbA[1], 1);
        MBAR_EXPECT(mbA[0], QG_STAGE_BYTES);
        MBAR_EXPECT(mbA[1], QG_STAGE_BYTES);
    }
    __syncthreads();
    if (t == 0) { issue_stage(0); issue_stage(1); }

    int ph[2] = { 0, 0 };

    for (int ks = 0; ks < 16; ks++) {
        const int bufi = ks & 1;
        mbar_wait(mbA[bufi], (unsigned)ph[bufi]);
        ph[bufi] ^= 1;

        const unsigned Ab = smb + QG_A(bufi);
        const unsigned Bb = smb + QG_B(bufi);
#pragma unroll
        for (int kk = 0; kk < 4; kk++) {
            const unsigned kbb = kk * 32;
            unsigned af[4][4];
#pragma unroll
            for (int mi = 0; mi < 4; mi++)
                ldsm4(af[mi], Ab + aRow[mi] + ((aCb + kbb) ^ aSwz[mi]));
            unsigned bfp[2][4];
#pragma unroll
            for (int nip = 0; nip < 2; nip++)
                ldsm4(bfp[nip], Bb + bRow[nip] + ((bCb + kbb) ^ bSwz[nip]));
#pragma unroll
            for (int mi = 0; mi < 4; mi++)
#pragma unroll
                for (int nip = 0; nip < 2; nip++) {
                    mma_f16(acc[mi][2 * nip],     af[mi][0], af[mi][1], af[mi][2], af[mi][3],
                            bfp[nip][0], bfp[nip][1]);
                    mma_f16(acc[mi][2 * nip + 1], af[mi][0], af[mi][1], af[mi][2], af[mi][3],
                            bfp[nip][2], bfp[nip][3]);
                }
        }

        if (ks + 2 < 16) {
            if (t == 0) MBAR_EXPECT(mbA[bufi], QG_STAGE_BYTES);
            __syncthreads();
            if (t == 0) issue_stage(ks + 2);
        }
    }

#pragma unroll
    for (int mi = 0; mi < 4; mi++) {
#pragma unroll
        for (int ni = 0; ni < 4; ni++) {
            int row = m0 + wm * 64 + mi * 16 + lr;
            int col = n0 + wn * 32 + ni * 8 + 2 * lc;
            *(__half2*)&C[(size_t)row * E_DIM + col] =
                __floats2half2_rn(acc[mi][ni][0], acc[mi][ni][1]);
            *(__half2*)&C[(size_t)(row + 8) * E_DIM + col] =
                __floats2half2_rn(acc[mi][ni][2], acc[mi][ni][3]);
        }
    }
}

// ---------------------------------------------------------------------------
// Kernel 2: per-head L2 norm -> blocked/swizzled Q/K. Q gets g*log2e folded
// (scores land in the log2 domain for ex2-based softmax).
// ---------------------------------------------------------------------------
__global__ __launch_bounds__(256) void norm_heads(const float* __restrict__ gptr)
{
    int warp = (blockIdx.x * blockDim.x + threadIdx.x) >> 5;
    int lane = threadIdx.x & 31;
    const int total = M_TOT * H_NUM;
    if (warp >= total) return;

    const __half* src = (blockIdx.y == 0) ? g_Qr : g_Kr;
    __half*       dst = (blockIdx.y == 0) ? g_Qb : g_Kb;
    float         sc  = (blockIdx.y == 0) ? gptr[0] * 1.4426950408889634f : 1.0f;

    __half2 v = ((const __half2*)(src + (size_t)warp * 64))[lane];
    float2 vf = __half22float2(v);
    float ss = vf.x * vf.x + vf.y * vf.y;
#pragma unroll
    for (int m = 16; m > 0; m >>= 1) ss += __shfl_xor_sync(0xffffffffu, ss, m);
    float inv = sc / fmaxf(sqrtf(ss), 1e-12f);

    const int h  = warp & 15;
    const int bs = warp >> 4;
    const int b  = bs >> 11;
    const int s  = bs & 2047;
    const int wchunk = (lane >> 2) ^ (s & 7);
    size_t base = ((size_t)(b * H_NUM + h) * S_LEN + s) * 64;
    *(__half2*)&dst[base + wchunk * 8 + (lane & 3) * 2] =
        __floats2half2_rn(vf.x * inv, vf.y * inv);
}

// ---------------------------------------------------------------------------
// Kernel 3: V transpose -> blocked/swizzled per-head per-ktile V^T.
// ---------------------------------------------------------------------------
__global__ __launch_bounds__(256) void transpose_v()
{
    __shared__ __half tile[32][66];
    const int s0 = blockIdx.x * 32;
    const int h  = blockIdx.y;
    const int b  = blockIdx.z;
    const int tx = threadIdx.x;
    const int ty = threadIdx.y;
    const int tid = ty * 32 + tx;

#pragma unroll
    for (int j = 0; j < 4; j++) {
        int r = ty + 8 * j;
        *(__half2*)&tile[r][2 * tx] =
            *(const __half2*)&g_Vh[(size_t)(b * S_LEN + s0 + r) * E_DIM + h * 64 + 2 * tx];
    }
    __syncthreads();

    const int d   = tid >> 2;
    const int sp0 = (tid & 3) * 4;
    const int kt  = s0 >> 6;
    size_t base = ((size_t)(b * H_NUM + h) * 32 + kt) * 4096 + (size_t)d * 64;
#pragma unroll
    for (int k = 0; k < 4; k++) {
        int sp = sp0 + k;
        int sb = (s0 & 63) + 2 * sp;
        int byte = sb * 2;
        int wchunk = (byte >> 4) ^ (d & 7);
        __half2 v = __halves2half2(tile[2 * sp][d], tile[2 * sp + 1][d]);
        *(__half2*)&g_Vtb[base + wchunk * 8 + ((byte & 15) >> 1)] = v;
    }
}

// ---------------------------------------------------------------------------
// Kernel 4: flash attention. Br=128, Bc=64, P register-resident.
// Softmax: P = 2^s via ex2.approx.f16x2 (half the MUFU ops, packed output).
// Row sums via ones-B MMA into a dedicated fp32 accumulator (no FADD chain,
// no epilogue shuffles). 8KB bulk K/V tiles, 4-buffer ring.
// ---------------------------------------------------------------------------
#define AT_Q     64
#define AT_QB    16384
#define AT_K(buf) (64 + AT_QB + (buf) * 8192)
#define AT_V(buf) (64 + AT_QB + 4 * 8192 + (buf) * 8192)
#define AT_PAIR_BYTES 32768u
#define ATTN_SMEM (64 + AT_QB + 8 * 8192)         // 81984 B

__global__ __launch_bounds__(256, 2) void attn_kernel(float* __restrict__ out)
{
    extern __shared__ __align__(16) char smc[];
    const unsigned smb = (unsigned)__cvta_generic_to_shared(smc);
    const unsigned mbA[2] = { smb, smb + 8 };

    const int b     = blockIdx.z;
    const int h     = blockIdx.y;
    const int q0    = blockIdx.x * 128;
    const int t     = threadIdx.x;
    const int warp  = t >> 5;
    const int lane  = t & 31;
    const int lr    = lane >> 2;
    const int lc    = lane & 3;
    const int r0    = warp * 16;

    const int l7 = lane & 7;
    const int jA_row = (lane >> 3) & 1;
    const int jA_col = (lane >> 4) & 1;
    const int jB_row = (lane >> 4) & 1;
    const int jB_col = (lane >> 3) & 1;

    const int rowA = r0 + jA_row * 8 + l7;
    const unsigned aRow = (unsigned)rowA * 128;
    const unsigned aSwz = (unsigned)(rowA & 7) << 4;
    const unsigned aCb  = (unsigned)jA_col * 16;
    unsigned nRow[4], nSwz[4];
#pragma unroll
    for (int np = 0; np < 4; np++) {
        int row = np * 16 + jB_row * 8 + l7;
        nRow[np] = (unsigned)row * 128;
        nSwz[np] = (unsigned)(row & 7) << 4;
    }
    const unsigned nCb = (unsigned)jB_col * 16;

    const size_t head = (size_t)(b * H_NUM + h);
    const __half* Qblk = g_Qb  + (head * S_LEN + q0) * 64;
    const __half* Kblk = g_Kb  + head * S_LEN * 64;
    const __half* Vblk = g_Vtb + head * S_LEN * 64;

    auto issue_pair = [&](int p) {     // thread 0 only
#pragma unroll
        for (int j = 0; j < 2; j++) {
            const int kt   = 2 * p + j;
            const int bufi = kt & 3;
            bulk_cp(smb + AT_K(bufi), Kblk + (size_t)kt * 4096, 8192, mbA[p & 1]);
            bulk_cp(smb + AT_V(bufi), Vblk + (size_t)kt * 4096, 8192, mbA[p & 1]);
        }
    };

    if (t == 0) {
        MBAR_INIT(mbA[0], 1); MBAR_INIT(mbA[1], 1);
        MBAR_EXPECT(mbA[0], AT_PAIR_BYTES);
        MBAR_EXPECT(mbA[1], AT_PAIR_BYTES);
    }
#pragma unroll
    for (int i = 0; i < 4; i++) {
        int s = t + i * 256;
        *(uint4*)(smc + AT_Q + s * 16) = *(const uint4*)(Qblk + s * 8);
    }
    __syncthreads();
    if (t == 0) { issue_pair(0); issue_pair(1); }

    unsigned qf[4][4];
#pragma unroll
    for (int kk = 0; kk < 4; kk++)
        ldsm4(qf[kk], smb + AT_Q + aRow + ((aCb + kk * 32) ^ aSwz));

    float oc[8][4];
#pragma unroll
    for (int ni = 0; ni < 8; ni++)
#pragma unroll
        for (int r = 0; r < 4; r++) oc[ni][r] = 0.0f;
    float ls[4] = { 0.0f, 0.0f, 0.0f, 0.0f };   // row-sum accumulator (ones-MMA)

    int ph[2] = { 0, 0 };

    for (int p = 0; p < 16; p++) {
        const int mbw = p & 1;
        mbar_wait(mbA[mbw], (unsigned)ph[mbw]);
        ph[mbw] ^= 1;

#pragma unroll
        for (int half = 0; half < 2; half++) {
            const int bufi = 2 * mbw + half;
            const unsigned Kb = smb + AT_K(bufi);
            const unsigned Vb = smb + AT_V(bufi);

            // ---- S(log2) = Q K^T ----
            float sv[8][4];
#pragma unroll
            for (int ni = 0; ni < 8; ni++)
#pragma unroll
                for (int r = 0; r < 4; r++) sv[ni][r] = 0.0f;

#pragma unroll
            for (int kk = 0; kk < 4; kk++) {
                const unsigned kbb = nCb + kk * 32;
#pragma unroll
                for (int np = 0; np < 4; np++) {
                    unsigned bfp[4];
                    ldsm4(bfp, Kb + nRow[np] + (kbb ^ nSwz[np]));
                    mma_f16(sv[2 * np],     qf[kk][0], qf[kk][1], qf[kk][2], qf[kk][3],
                            bfp[0], bfp[1]);
                    mma_f16(sv[2 * np + 1], qf[kk][0], qf[kk][1], qf[kk][2], qf[kk][3],
                            bfp[2], bfp[3]);
                }
            }

            // ---- P = 2^S via fp16x2 MUFU (packed) ----
            unsigned pk0[8], pk1[8];
#pragma unroll
            for (int ni = 0; ni < 8; ni++) {
                unsigned u0 = pack_h2(sv[ni][0], sv[ni][1]);
                unsigned u1 = pack_h2(sv[ni][2], sv[ni][3]);
                asm("ex2.approx.f16x2 %0, %0;" : "+r"(u0));
                asm("ex2.approx.f16x2 %0, %0;" : "+r"(u1));
                pk0[ni] = u0;
                pk1[ni] = u1;
            }

            // ---- row sums via ones-B MMA; O += P @ V ----
#pragma unroll
            for (int j = 0; j < 4; j++) {
                const unsigned kbb = nCb + j * 32;
                unsigned a0 = pk0[2 * j],     a1 = pk1[2 * j];
                unsigned a2 = pk0[2 * j + 1], a3 = pk1[2 * j + 1];
                mma_f16(ls, a0, a1, a2, a3, ONE2, ONE2);
#pragma unroll
                for (int np = 0; np < 4; np++) {
                    unsigned bfp[4];
                    ldsm4(bfp, Vb + nRow[np] + (kbb ^ nSwz[np]));
                    mma_f16(oc[2 * np],     a0, a1, a2, a3, bfp[0], bfp[1]);
                    mma_f16(oc[2 * np + 1], a0, a1, a2, a3, bfp[2], bfp[3]);
                }
            }
        }

        if (p + 2 < 16) {
            if (t == 0) MBAR_EXPECT(mbA[mbw], AT_PAIR_BYTES);
            __syncthreads();
            if (t == 0) issue_pair(p + 2);
        }
    }

    // ---- epilogue: ls[0]/ls[2] hold row sums for rows lr / lr+8 ----
    float inv0 = 1.0f / ls[0];
    float inv1 = 1.0f / ls[2];

    int ra = q0 + r0 + lr;
#pragma unroll
    for (int ni = 0; ni < 8; ni++) {
        int col = h * D_HEAD + ni * 8 + 2 * lc;
        *(float2*)&out[((size_t)(b * S_LEN) + ra) * E_DIM + col] =
            make_float2(oc[ni][0] * inv0, oc[ni][1] * inv0);
        *(float2*)&out[((size_t)(b * S_LEN) + ra + 8) * E_DIM + col] =
            make_float2(oc[ni][2] * inv1, oc[ni][3] * inv1);
    }
}

// ---------------------------------------------------------------------------
extern "C" void kernel_launch(void* const* d_in, const int* in_sizes, int n_in,
                              void* d_out, int out_size)
{
    const float* x  = (const float*)d_in[0];
    const float* Wq = (const float*)d_in[1];
    const float* Wk = (const float*)d_in[2];
    const float* Wv = (const float*)d_in[3];
    const float* g  = (const float*)d_in[4];
    float* out = (float*)d_out;

    // 0) fp32 -> fp16 blocked/swizzled conversion of all GEMM inputs
    cvt_all<<<(NCVT8 + 255) / 256, 256>>>(x, Wq, Wk, Wv);

    // 1) QKV projections (16KB bulk staging, zero LDGSTS in mainloop)
    {
        cudaFuncSetAttribute(qkv_gemm, cudaFuncAttributeMaxDynamicSharedMemorySize,
                             QKV_SMEM);
        dim3 grid(E_DIM / 128, M_TOT / 128, 3);
        qkv_gemm<<<grid, 256, QKV_SMEM>>>();
    }

    // 2) per-head L2 norm -> blocked/swizzled Q/K (g*log2e folded into Q)
    {
        const int chunks = M_TOT * H_NUM;
        dim3 ngrid(chunks / 8, 2);
        norm_heads<<<ngrid, 256>>>(g);
    }

    // 3) V transpose -> blocked/swizzled per-ktile V^T
    {
        dim3 tgrid(S_LEN / 32, H_NUM, B_NUM);
        dim3 tblk(32, 8);
        transpose_v<<<tgrid, tblk>>>();
    }

    // 4) Flash attention (ex2.f16x2 softmax, ones-MMA row sums, bulk staging)
    {
        cudaFuncSetAttribute(attn_kernel, cudaFuncAttributeMaxDynamicSharedMemorySize,
                             ATTN_SMEM);
        dim3 agrid(S_LEN / 128, H_NUM, B_NUM);
        attn_kernel<<<agrid, 256, ATTN_SMEM>>>(out);
    }
}